// round 8
// baseline (speedup 1.0000x reference)
#include <cuda_runtime.h>
#include <cuda_fp16.h>
#include <cstdint>

// Problem constants
#define B_   32
#define C_   128
#define H_   64
#define W_   64
#define O_   256
#define K_   1152            // C*9
#define M_   32768           // B*32*32

// Static device scratch
__device__ __half g_pa[(size_t)M_ * K_];   // patches fp16, [m][k]
__device__ __half g_wb[O_ * K_];           // weight fp16,  [o][k]

// ---------------------------------------------------------------------------
// Kernel 1: bilinear im2col, smem-staged, fp16 output.
//   grid = (1024, 4): x -> (b,p), y -> 32-channel chunk (was a serial loop).
// ---------------------------------------------------------------------------
#define OUT_STRIDE 292   // fp16 per staged q-row (288 data + 4 pad)
#define XS_BYTES   32768
#define IM2COL_SMEM (XS_BYTES + 32 * OUT_STRIDE * 2)   // 51456

__global__ __launch_bounds__(256, 4)
void im2col_kernel(const float* __restrict__ x,
                   const float* __restrict__ sh_p,
                   const float* __restrict__ sw_p)
{
    extern __shared__ char sm[];
    float* xs = (float*)sm;                              // [c][4][64]
    __half* ohi = (__half*)(sm + XS_BYTES);              // [32][OUT_STRIDE]

    const int t  = threadIdx.x;
    const int b  = blockIdx.x >> 5;
    const int p  = blockIdx.x & 31;
    const int c0 = blockIdx.y * 32;

    const float sh = __ldg(sh_p);
    const float sw = __ldg(sw_p);

    const float ph = (float)p * sh - 1.0f;
    const float fh = floorf(ph);
    const int   h0 = (int)fh;
    const float ah = ph - fh;

    const int q  = t & 31;
    const int cg = t >> 5;           // 0..7
    const float pw = (float)q * sw - 1.0f;
    const float fw = floorf(pw);
    const int   w0 = (int)fw;
    const float aw = pw - fw;

    // ---- phase 1: coalesced x load ----
    {
        const float4* xg = (const float4*)x;
        for (int i = t; i < 2048; i += 256) {
            const int cl  = i >> 6;
            const int rem = i & 63;
            const int r   = rem >> 4;
            const int w4  = rem & 15;
            const int hr  = h0 + r;
            float4 v = make_float4(0.f, 0.f, 0.f, 0.f);
            if ((unsigned)hr < (unsigned)H_)
                v = xg[((size_t)(b * C_ + c0 + cl) * H_ + hr) * 16 + w4];
            ((float4*)xs)[i] = v;
        }
    }
    __syncthreads();

    // ---- phase 2: compute 9 taps for 4 channels per thread ----
#pragma unroll
    for (int i = 0; i < 4; i++) {
        const int cl = cg * 4 + i;
        const float* xr = xs + cl * 256;

        float v[4][4];
#pragma unroll
        for (int r = 0; r < 4; r++)
#pragma unroll
            for (int j = 0; j < 4; j++) {
                const int wc = w0 + j;
                v[r][j] = ((unsigned)wc < (unsigned)W_) ? xr[r * 64 + wc] : 0.0f;
            }

        float cwv[4][3];
#pragma unroll
        for (int r = 0; r < 4; r++)
#pragma unroll
            for (int kw = 0; kw < 3; kw++)
                cwv[r][kw] = (1.0f - aw) * v[r][kw] + aw * v[r][kw + 1];

        __half* oh = ohi + q * OUT_STRIDE + cl * 9;
#pragma unroll
        for (int kh = 0; kh < 3; kh++)
#pragma unroll
            for (int kw = 0; kw < 3; kw++) {
                const float val = (1.0f - ah) * cwv[kh][kw] + ah * cwv[kh + 1][kw];
                oh[kh * 3 + kw] = __float2half_rn(val);
            }
    }
    __syncthreads();

    // ---- phase 3: coalesced store (72 uint2 per q) ----
    {
        const size_t mrow = (size_t)(b * 1024 + p * 32);
        for (int i = t; i < 2304; i += 256) {
            const int qq = i / 72;
            const int j  = i - qq * 72;
            const uint2 vh = *(const uint2*)((const char*)ohi + qq * (OUT_STRIDE * 2) + j * 8);
            const size_t gd = ((mrow + qq) * K_ + c0 * 9) * 2 + j * 8;   // bytes
            *(uint2*)((char*)g_pa + gd) = vh;
        }
    }
}

// ---------------------------------------------------------------------------
// Kernel 2: weight fp32 [o][k] -> fp16 [o][k]
// ---------------------------------------------------------------------------
__global__ void wconv_kernel(const float* __restrict__ w)
{
    int idx = blockIdx.x * blockDim.x + threadIdx.x;
    g_wb[idx] = __float2half_rn(w[idx]);
}

// ---------------------------------------------------------------------------
// Kernel 3: fp16 GEMM via mma.sync.m16n8k16, 3-stage cp.async, 2 CTAs/SM.
//   CTA: 256 threads, D[128m x 128n]; warp grid 2(m) x 4(n), warp tile 64x32.
//   Invariant: exactly ONE commit_group per iteration.
// ---------------------------------------------------------------------------
#define BK 32
#define NK (K_ / BK)            // 36
#define ROWB 80                 // padded row stride (64B data + 16B pad)
#define MAT_BYTES (128 * ROWB)  // 10240
#define STAGE_BYTES (2 * MAT_BYTES)   // A, B -> 20480
#define SMEM_BYTES (3 * STAGE_BYTES)  // 61440 (epilogue: 64x132 floats = 33.8KB)

__device__ __forceinline__ uint32_t cvta_s(const void* p)
{
    uint32_t a;
    asm("{ .reg .u64 t; cvta.to.shared.u64 t, %1; cvt.u32.u64 %0, t; }"
        : "=r"(a) : "l"(p));
    return a;
}

__device__ __forceinline__ void cp16(uint32_t s, const void* g)
{
    asm volatile("cp.async.ca.shared.global [%0], [%1], 16;"
                 :: "r"(s), "l"(g));
}

__device__ __forceinline__ void ldsm4(uint32_t a, uint32_t* r)
{
    asm volatile("ldmatrix.sync.aligned.m8n8.x4.shared.b16 {%0,%1,%2,%3}, [%4];"
                 : "=r"(r[0]), "=r"(r[1]), "=r"(r[2]), "=r"(r[3]) : "r"(a));
}

__device__ __forceinline__ void mma16816(float* d, const uint32_t* a,
                                         const uint32_t* b)
{
    asm volatile(
        "mma.sync.aligned.m16n8k16.row.col.f32.f16.f16.f32 "
        "{%0,%1,%2,%3}, {%4,%5,%6,%7}, {%8,%9}, {%0,%1,%2,%3};"
        : "+f"(d[0]), "+f"(d[1]), "+f"(d[2]), "+f"(d[3])
        : "r"(a[0]), "r"(a[1]), "r"(a[2]), "r"(a[3]), "r"(b[0]), "r"(b[1]));
}

__global__ __launch_bounds__(256, 2)
void gemm_kernel(const float* __restrict__ bias, float* __restrict__ out)
{
    extern __shared__ char smem[];
    const uint32_t sbase = cvta_s(smem);

    const int tid  = threadIdx.x;
    const int lane = tid & 31;
    const int wid  = tid >> 5;
    const int m0   = blockIdx.y * 128;
    const int o0   = blockIdx.x * 128;

    // cp.async loader: 1024 16B chunks per stage, 256 threads -> 4 each
    // (2 contiguous for A, 2 contiguous for B)
    const int lrow = tid >> 1;           // 0..127
    const int lh   = (tid & 1) * 32;     // byte offset within 64B row
    const char* gA = (const char*)g_pa + ((size_t)(m0 + lrow) * K_) * 2 + lh;
    const char* gB = (const char*)g_wb + ((size_t)(o0 + lrow) * K_) * 2 + lh;
    const uint32_t soff = lrow * ROWB + lh;

#define LOAD_STAGE(stage, buf)                                                 \
    {                                                                          \
        const uint32_t sb = sbase + (buf) * STAGE_BYTES + soff;                \
        const size_t go = (size_t)(stage) * (BK * 2);                          \
        cp16(sb,                  gA + go);                                    \
        cp16(sb + 16,             gA + go + 16);                               \
        cp16(sb + MAT_BYTES,      gB + go);                                    \
        cp16(sb + MAT_BYTES + 16, gB + go + 16);                               \
    }

    // warp grid: 2 (m) x 4 (n); warp tile 64m x 32n
    const int wm = (wid & 1) * 64;
    const int wn = (wid >> 1) * 32;

    const int a_row = lane & 15;
    const int a_col = (lane >> 4) << 3;
    const int b_row = (lane & 7) + ((lane >> 4) << 3);
    const int b_col = lane & 8;

    float acc[4][4][4];
#pragma unroll
    for (int i = 0; i < 4; i++)
#pragma unroll
        for (int j = 0; j < 4; j++)
#pragma unroll
            for (int r = 0; r < 4; r++) acc[i][j][r] = 0.0f;

    LOAD_STAGE(0, 0);
    asm volatile("cp.async.commit_group;");
    LOAD_STAGE(1, 1);
    asm volatile("cp.async.commit_group;");

    for (int it = 0; it < NK; it++) {
        asm volatile("cp.async.wait_group 1;");
        __syncthreads();

        const uint32_t stg = sbase + (it % 3) * STAGE_BYTES;
        const uint32_t sA = stg;
        const uint32_t sB = stg + MAT_BYTES;

#pragma unroll
        for (int ks = 0; ks < 2; ks++) {
            const int kk = ks * 16;
            uint32_t a[4][4], bfr[2][4];
#pragma unroll
            for (int i = 0; i < 4; i++) {
                uint32_t off = (uint32_t)((wm + i * 16 + a_row) * ROWB
                                          + (kk + a_col) * 2);
                ldsm4(sA + off, a[i]);
            }
#pragma unroll
            for (int j2 = 0; j2 < 2; j2++) {
                uint32_t off = (uint32_t)((wn + j2 * 16 + b_row) * ROWB
                                          + (kk + b_col) * 2);
                ldsm4(sB + off, bfr[j2]);
            }
#pragma unroll
            for (int i = 0; i < 4; i++)
#pragma unroll
                for (int j = 0; j < 4; j++)
                    mma16816(acc[i][j], a[i], &bfr[j >> 1][(j & 1) * 2]);
        }

        __syncthreads();
        if (it + 2 < NK) LOAD_STAGE(it + 2, (it + 2) % 3);
        asm volatile("cp.async.commit_group;");   // exactly one commit per iter
    }

    asm volatile("cp.async.wait_group 0;");
    __syncthreads();

    // ---- epilogue: two 64-o halves staged through smem ----
    float* eb = (float*)smem;            // [64 o][132 m] floats = 33.8 KB
    const int bidx = m0 >> 10;
    const int pq0  = m0 & 1023;

#pragma unroll
    for (int h = 0; h < 2; h++) {
        const int oh0 = h * 64;
        // warps whose wn lies in this half write their acc
        if (wn >= oh0 && wn < oh0 + 64) {
#pragma unroll
            for (int i = 0; i < 4; i++) {
                int ml = wm + i * 16 + (lane >> 2);
#pragma unroll
                for (int j = 0; j < 4; j++) {
                    int ol = wn - oh0 + j * 8 + (lane & 3) * 2;
                    eb[(size_t)ol * 132 + ml]           = acc[i][j][0];
                    eb[(size_t)(ol + 1) * 132 + ml]     = acc[i][j][1];
                    eb[(size_t)ol * 132 + ml + 8]       = acc[i][j][2];
                    eb[(size_t)(ol + 1) * 132 + ml + 8] = acc[i][j][3];
                }
            }
        }
        __syncthreads();

        // all 256 threads store 64 o x 128 m
        const int oo   = tid >> 2;           // 0..63
        const int quad = tid & 3;            // 32 m each
        const int og   = o0 + oh0 + oo;
        const float bv = __ldg(bias + og);
        float* op = out + (size_t)bidx * (O_ * 1024)
                  + (size_t)og * 1024 + pq0 + quad * 32;
        const float* sp = eb + (size_t)oo * 132 + quad * 32;
#pragma unroll
        for (int i = 0; i < 8; i++) {
            float4 vv = *(const float4*)(sp + i * 4);
            vv.x += bv; vv.y += bv; vv.z += bv; vv.w += bv;
            *(float4*)(op + i * 4) = vv;
        }
        __syncthreads();
    }
#undef LOAD_STAGE
}

// ---------------------------------------------------------------------------
extern "C" void kernel_launch(void* const* d_in, const int* in_sizes, int n_in,
                              void* d_out, int out_size)
{
    const float* x    = (const float*)d_in[0];
    const float* w    = (const float*)d_in[1];
    const float* bias = (const float*)d_in[2];
    const float* sh   = (const float*)d_in[3];
    const float* sw   = (const float*)d_in[4];
    float* out = (float*)d_out;

    cudaFuncSetAttribute(im2col_kernel,
                         cudaFuncAttributeMaxDynamicSharedMemorySize, IM2COL_SMEM);
    cudaFuncSetAttribute(gemm_kernel,
                         cudaFuncAttributeMaxDynamicSharedMemorySize, SMEM_BYTES);

    im2col_kernel<<<dim3(1024, 4), 256, IM2COL_SMEM>>>(x, sh, sw);
    wconv_kernel<<<(O_ * K_) / 256, 256>>>(w);
    gemm_kernel<<<dim3(2, 256), 256, SMEM_BYTES>>>(bias, out);
}

// round 9
// speedup vs baseline: 1.0028x; 1.0028x over previous
#include <cuda_runtime.h>
#include <cuda_fp16.h>
#include <cstdint>

// Problem constants
#define B_   32
#define C_   128
#define H_   64
#define W_   64
#define O_   256
#define K_   1152            // C*9
#define M_   32768           // B*32*32

// Static device scratch
__device__ __half g_pa[(size_t)M_ * K_];   // patches fp16, [m][k]
__device__ __half g_wb[O_ * K_];           // weight fp16,  [o][k]

// ---------------------------------------------------------------------------
// Kernel 1: bilinear im2col, smem-staged, fp16 output (R7 version).
// ---------------------------------------------------------------------------
#define OUT_STRIDE 292
#define XS_BYTES   32768
#define IM2COL_SMEM (XS_BYTES + 32 * OUT_STRIDE * 2)   // 51456

__global__ __launch_bounds__(256, 4)
void im2col_kernel(const float* __restrict__ x,
                   const float* __restrict__ sh_p,
                   const float* __restrict__ sw_p)
{
    extern __shared__ char sm[];
    float* xs = (float*)sm;                              // [c][4][64]
    __half* ohi = (__half*)(sm + XS_BYTES);              // [32][OUT_STRIDE]

    const int t = threadIdx.x;
    const int b = blockIdx.x >> 5;
    const int p = blockIdx.x & 31;

    const float sh = __ldg(sh_p);
    const float sw = __ldg(sw_p);

    const float ph = (float)p * sh - 1.0f;
    const float fh = floorf(ph);
    const int   h0 = (int)fh;
    const float ah = ph - fh;

    const int q  = t & 31;
    const int cg = t >> 5;
    const float pw = (float)q * sw - 1.0f;
    const float fw = floorf(pw);
    const int   w0 = (int)fw;
    const float aw = pw - fw;

    for (int cc = 0; cc < 4; cc++) {
        const int c0 = cc * 32;

        {
            const float4* xg = (const float4*)x;
            for (int i = t; i < 2048; i += 256) {
                const int cl  = i >> 6;
                const int rem = i & 63;
                const int r   = rem >> 4;
                const int w4  = rem & 15;
                const int hr  = h0 + r;
                float4 v = make_float4(0.f, 0.f, 0.f, 0.f);
                if ((unsigned)hr < (unsigned)H_)
                    v = xg[((size_t)(b * C_ + c0 + cl) * H_ + hr) * 16 + w4];
                ((float4*)xs)[i] = v;
            }
        }
        __syncthreads();

#pragma unroll
        for (int i = 0; i < 4; i++) {
            const int cl = cg * 4 + i;
            const float* xr = xs + cl * 256;

            float v[4][4];
#pragma unroll
            for (int r = 0; r < 4; r++)
#pragma unroll
                for (int j = 0; j < 4; j++) {
                    const int wc = w0 + j;
                    v[r][j] = ((unsigned)wc < (unsigned)W_) ? xr[r * 64 + wc] : 0.0f;
                }

            float cwv[4][3];
#pragma unroll
            for (int r = 0; r < 4; r++)
#pragma unroll
                for (int kw = 0; kw < 3; kw++)
                    cwv[r][kw] = (1.0f - aw) * v[r][kw] + aw * v[r][kw + 1];

            __half* oh = ohi + q * OUT_STRIDE + cl * 9;
#pragma unroll
            for (int kh = 0; kh < 3; kh++)
#pragma unroll
                for (int kw = 0; kw < 3; kw++) {
                    const float val = (1.0f - ah) * cwv[kh][kw] + ah * cwv[kh + 1][kw];
                    oh[kh * 3 + kw] = __float2half_rn(val);
                }
        }
        __syncthreads();

        {
            const size_t mrow = (size_t)(b * 1024 + p * 32);
            for (int i = t; i < 2304; i += 256) {
                const int qq = i / 72;
                const int j  = i - qq * 72;
                const uint2 vh = *(const uint2*)((const char*)ohi + qq * (OUT_STRIDE * 2) + j * 8);
                const size_t gd = ((mrow + qq) * K_ + c0 * 9) * 2 + j * 8;
                *(uint2*)((char*)g_pa + gd) = vh;
            }
        }
        __syncthreads();
    }
}

// ---------------------------------------------------------------------------
// Kernel 2: weight fp32 [o][k] -> fp16 [o][k]
// ---------------------------------------------------------------------------
__global__ void wconv_kernel(const float* __restrict__ w)
{
    int idx = blockIdx.x * blockDim.x + threadIdx.x;
    g_wb[idx] = __float2half_rn(w[idx]);
}

// ---------------------------------------------------------------------------
// Kernel 3: fp16 GEMM, BK=64, XOR-swizzled smem, ONE sync per iteration.
//   256 threads, 2 CTAs/SM. Warp grid 2(m) x 4(n), warp tile 64m x 32n.
// ---------------------------------------------------------------------------
#define BK 64
#define NK (K_ / BK)            // 18
#define MAT_BYTES (128 * 128)   // 16384 (128 rows x 128B, swizzled)
#define STAGE_BYTES (2 * MAT_BYTES)   // 32768
#define SMEM_BYTES (3 * STAGE_BYTES)  // 98304

// swizzled smem offset for (row, 16B-chunk)
#define SWO(row, chunk) ((uint32_t)((row) * 128 + (((chunk) ^ ((row) & 7)) << 4)))

__device__ __forceinline__ uint32_t cvta_s(const void* p)
{
    uint32_t a;
    asm("{ .reg .u64 t; cvta.to.shared.u64 t, %1; cvt.u32.u64 %0, t; }"
        : "=r"(a) : "l"(p));
    return a;
}

__device__ __forceinline__ void cp16(uint32_t s, const void* g)
{
    asm volatile("cp.async.ca.shared.global [%0], [%1], 16;"
                 :: "r"(s), "l"(g));
}

__device__ __forceinline__ void ldsm4(uint32_t a, uint32_t* r)
{
    asm volatile("ldmatrix.sync.aligned.m8n8.x4.shared.b16 {%0,%1,%2,%3}, [%4];"
                 : "=r"(r[0]), "=r"(r[1]), "=r"(r[2]), "=r"(r[3]) : "r"(a));
}

__device__ __forceinline__ void mma16816(float* d, const uint32_t* a,
                                         const uint32_t* b)
{
    asm volatile(
        "mma.sync.aligned.m16n8k16.row.col.f32.f16.f16.f32 "
        "{%0,%1,%2,%3}, {%4,%5,%6,%7}, {%8,%9}, {%0,%1,%2,%3};"
        : "+f"(d[0]), "+f"(d[1]), "+f"(d[2]), "+f"(d[3])
        : "r"(a[0]), "r"(a[1]), "r"(a[2]), "r"(a[3]), "r"(b[0]), "r"(b[1]));
}

__global__ __launch_bounds__(256, 2)
void gemm_kernel(const float* __restrict__ bias, float* __restrict__ out)
{
    extern __shared__ char smem[];
    const uint32_t sbase = cvta_s(smem);

    const int tid  = threadIdx.x;
    const int lane = tid & 31;
    const int wid  = tid >> 5;
    const int m0   = blockIdx.y * 128;
    const int o0   = blockIdx.x * 128;

    // loader: per stage 128 rows x 8 chunks x 2 matrices = 2048 chunks / 256 thr
    const int lrow = tid >> 1;                  // 0..127
    const int lc0  = (tid & 1) * 4;             // first of 4 chunks
    const char* gA = (const char*)g_pa + ((size_t)(m0 + lrow) * K_) * 2;
    const char* gB = (const char*)g_wb + ((size_t)(o0 + lrow) * K_) * 2;

#define LOAD_STAGE(stage, buf)                                                 \
    {                                                                          \
        const uint32_t sb = sbase + (buf) * STAGE_BYTES;                       \
        const size_t gk = (size_t)(stage) * 128;                               \
        _Pragma("unroll")                                                      \
        for (int ci = 0; ci < 4; ci++) {                                       \
            const int ch = lc0 + ci;                                           \
            cp16(sb + SWO(lrow, ch),             gA + gk + ch * 16);           \
            cp16(sb + MAT_BYTES + SWO(lrow, ch), gB + gk + ch * 16);           \
        }                                                                      \
    }

    // warp grid: 2 (m) x 4 (n); warp tile 64m x 32n
    const int wm = (wid & 1) * 64;
    const int wn = (wid >> 1) * 32;

    const int a_row = lane & 15;
    const int a_col8 = (lane >> 4);             // 0/1: which 8-col group
    const int b_row = (lane & 7) + ((lane >> 4) << 3);
    const int b_col8 = (lane >> 3) & 1;

    float acc[4][4][4];
#pragma unroll
    for (int i = 0; i < 4; i++)
#pragma unroll
        for (int j = 0; j < 4; j++)
#pragma unroll
            for (int r = 0; r < 4; r++) acc[i][j][r] = 0.0f;

    LOAD_STAGE(0, 0);
    asm volatile("cp.async.commit_group;");
    LOAD_STAGE(1, 1);
    asm volatile("cp.async.commit_group;");

    for (int it = 0; it < NK; it++) {
        asm volatile("cp.async.wait_group 1;");
        __syncthreads();

        // issue next stage load BEFORE compute (overlaps with mma work).
        // buffer (it+2)%3 == (it-1)%3: all warps passed the sync above, so
        // every warp has finished iteration it-1's reads of that buffer.
        if (it + 2 < NK) LOAD_STAGE(it + 2, (it + 2) % 3);
        asm volatile("cp.async.commit_group;");   // exactly one commit per iter

        const uint32_t stg = sbase + (it % 3) * STAGE_BYTES;
        const uint32_t sA = stg;
        const uint32_t sB = stg + MAT_BYTES;

#pragma unroll
        for (int ks = 0; ks < 4; ks++) {
            // 16B-chunk index along k for this k16 step
            const int ca = ks * 2 + a_col8;      // A: (kk + a_col)/8
            const int cb = ks * 2 + b_col8;      // B: (kk + b_col)/8
            uint32_t a[4][4], bfr[2][4];
#pragma unroll
            for (int i = 0; i < 4; i++)
                ldsm4(sA + SWO(wm + i * 16 + a_row, ca), a[i]);
#pragma unroll
            for (int j2 = 0; j2 < 2; j2++)
                ldsm4(sB + SWO(wn + j2 * 16 + b_row, cb), bfr[j2]);
#pragma unroll
            for (int i = 0; i < 4; i++)
#pragma unroll
                for (int j = 0; j < 4; j++)
                    mma16816(acc[i][j], a[i], &bfr[j >> 1][(j & 1) * 2]);
        }
        // no second sync: next iteration's top sync provides the ordering
    }

    asm volatile("cp.async.wait_group 0;");
    __syncthreads();

    // ---- epilogue: two 64-o halves staged through smem ----
    float* eb = (float*)smem;            // [64 o][132 m] floats = 33.8 KB
    const int bidx = m0 >> 10;
    const int pq0  = m0 & 1023;

#pragma unroll
    for (int h = 0; h < 2; h++) {
        const int oh0 = h * 64;
        if (wn >= oh0 && wn < oh0 + 64) {
#pragma unroll
            for (int i = 0; i < 4; i++) {
                int ml = wm + i * 16 + (lane >> 2);
#pragma unroll
                for (int j = 0; j < 4; j++) {
                    int ol = wn - oh0 + j * 8 + (lane & 3) * 2;
                    eb[(size_t)ol * 132 + ml]           = acc[i][j][0];
                    eb[(size_t)(ol + 1) * 132 + ml]     = acc[i][j][1];
                    eb[(size_t)ol * 132 + ml + 8]       = acc[i][j][2];
                    eb[(size_t)(ol + 1) * 132 + ml + 8] = acc[i][j][3];
                }
            }
        }
        __syncthreads();

        const int oo   = tid >> 2;
        const int quad = tid & 3;
        const int og   = o0 + oh0 + oo;
        const float bv = __ldg(bias + og);
        float* op = out + (size_t)bidx * (O_ * 1024)
                  + (size_t)og * 1024 + pq0 + quad * 32;
        const float* sp = eb + (size_t)oo * 132 + quad * 32;
#pragma unroll
        for (int i = 0; i < 8; i++) {
            float4 vv = *(const float4*)(sp + i * 4);
            vv.x += bv; vv.y += bv; vv.z += bv; vv.w += bv;
            *(float4*)(op + i * 4) = vv;
        }
        __syncthreads();
    }
#undef LOAD_STAGE
}

// ---------------------------------------------------------------------------
extern "C" void kernel_launch(void* const* d_in, const int* in_sizes, int n_in,
                              void* d_out, int out_size)
{
    const float* x    = (const float*)d_in[0];
    const float* w    = (const float*)d_in[1];
    const float* bias = (const float*)d_in[2];
    const float* sh   = (const float*)d_in[3];
    const float* sw   = (const float*)d_in[4];
    float* out = (float*)d_out;

    cudaFuncSetAttribute(im2col_kernel,
                         cudaFuncAttributeMaxDynamicSharedMemorySize, IM2COL_SMEM);
    cudaFuncSetAttribute(gemm_kernel,
                         cudaFuncAttributeMaxDynamicSharedMemorySize, SMEM_BYTES);

    im2col_kernel<<<1024, 256, IM2COL_SMEM>>>(x, sh, sw);
    wconv_kernel<<<(O_ * K_) / 256, 256>>>(w);
    gemm_kernel<<<dim3(2, 256), 256, SMEM_BYTES>>>(bias, out);
}

// round 10
// speedup vs baseline: 1.1871x; 1.1838x over previous
#include <cuda_runtime.h>
#include <cuda_fp16.h>
#include <cstdint>

// Problem constants
#define B_   32
#define C_   128
#define H_   64
#define W_   64
#define O_   256
#define K_   1152            // C*9
#define M_   32768           // B*32*32

// Static device scratch
__device__ __half g_pa[(size_t)M_ * K_];   // patches fp16, [m][k]
__device__ __half g_wb[O_ * K_];           // weight fp16,  [o][k]

// ---------------------------------------------------------------------------
// Kernel 1: bilinear im2col, smem-staged, fp16 output (measured-best R7 form).
// ---------------------------------------------------------------------------
#define OUT_STRIDE 292
#define XS_BYTES   32768
#define IM2COL_SMEM (XS_BYTES + 32 * OUT_STRIDE * 2)   // 51456

__global__ __launch_bounds__(256, 4)
void im2col_kernel(const float* __restrict__ x,
                   const float* __restrict__ sh_p,
                   const float* __restrict__ sw_p)
{
    extern __shared__ char sm[];
    float* xs = (float*)sm;                              // [c][4][64]
    __half* ohi = (__half*)(sm + XS_BYTES);              // [32][OUT_STRIDE]

    const int t = threadIdx.x;
    const int b = blockIdx.x >> 5;
    const int p = blockIdx.x & 31;

    const float sh = __ldg(sh_p);
    const float sw = __ldg(sw_p);

    const float ph = (float)p * sh - 1.0f;
    const float fh = floorf(ph);
    const int   h0 = (int)fh;
    const float ah = ph - fh;

    const int q  = t & 31;
    const int cg = t >> 5;
    const float pw = (float)q * sw - 1.0f;
    const float fw = floorf(pw);
    const int   w0 = (int)fw;
    const float aw = pw - fw;

    for (int cc = 0; cc < 4; cc++) {
        const int c0 = cc * 32;

        {
            const float4* xg = (const float4*)x;
            for (int i = t; i < 2048; i += 256) {
                const int cl  = i >> 6;
                const int rem = i & 63;
                const int r   = rem >> 4;
                const int w4  = rem & 15;
                const int hr  = h0 + r;
                float4 v = make_float4(0.f, 0.f, 0.f, 0.f);
                if ((unsigned)hr < (unsigned)H_)
                    v = xg[((size_t)(b * C_ + c0 + cl) * H_ + hr) * 16 + w4];
                ((float4*)xs)[i] = v;
            }
        }
        __syncthreads();

#pragma unroll
        for (int i = 0; i < 4; i++) {
            const int cl = cg * 4 + i;
            const float* xr = xs + cl * 256;

            float v[4][4];
#pragma unroll
            for (int r = 0; r < 4; r++)
#pragma unroll
                for (int j = 0; j < 4; j++) {
                    const int wc = w0 + j;
                    v[r][j] = ((unsigned)wc < (unsigned)W_) ? xr[r * 64 + wc] : 0.0f;
                }

            float cwv[4][3];
#pragma unroll
            for (int r = 0; r < 4; r++)
#pragma unroll
                for (int kw = 0; kw < 3; kw++)
                    cwv[r][kw] = (1.0f - aw) * v[r][kw] + aw * v[r][kw + 1];

            __half* oh = ohi + q * OUT_STRIDE + cl * 9;
#pragma unroll
            for (int kh = 0; kh < 3; kh++)
#pragma unroll
                for (int kw = 0; kw < 3; kw++) {
                    const float val = (1.0f - ah) * cwv[kh][kw] + ah * cwv[kh + 1][kw];
                    oh[kh * 3 + kw] = __float2half_rn(val);
                }
        }
        __syncthreads();

        {
            const size_t mrow = (size_t)(b * 1024 + p * 32);
            for (int i = t; i < 2304; i += 256) {
                const int qq = i / 72;
                const int j  = i - qq * 72;
                const uint2 vh = *(const uint2*)((const char*)ohi + qq * (OUT_STRIDE * 2) + j * 8);
                const size_t gd = ((mrow + qq) * K_ + c0 * 9) * 2 + j * 8;
                *(uint2*)((char*)g_pa + gd) = vh;
            }
        }
        __syncthreads();
    }
}

// ---------------------------------------------------------------------------
// Kernel 2: weight fp32 [o][k] -> fp16 [o][k]
// ---------------------------------------------------------------------------
__global__ void wconv_kernel(const float* __restrict__ w)
{
    int idx = blockIdx.x * blockDim.x + threadIdx.x;
    g_wb[idx] = __float2half_rn(w[idx]);
}

// ---------------------------------------------------------------------------
// Kernel 3: fp16 GEMM, full-N tile: D[128m x 256n] per CTA (A read ONCE).
//   512 threads, 16 warps (2m x 8n), warp tile 64m x 32n. BK=64, 3 stages,
//   XOR-swizzled smem, one sync per iteration.
// ---------------------------------------------------------------------------
#define BK 64
#define NK (K_ / BK)              // 18
#define MATA_BYTES (128 * 128)    // 16 KB
#define MATB_BYTES (256 * 128)    // 32 KB
#define STAGE_BYTES (MATA_BYTES + MATB_BYTES)   // 49152
#define SMEM_BYTES (3 * STAGE_BYTES)            // 147456

#define SWO(row, chunk) ((uint32_t)((row) * 128 + (((chunk) ^ ((row) & 7)) << 4)))

__device__ __forceinline__ uint32_t cvta_s(const void* p)
{
    uint32_t a;
    asm("{ .reg .u64 t; cvta.to.shared.u64 t, %1; cvt.u32.u64 %0, t; }"
        : "=r"(a) : "l"(p));
    return a;
}

__device__ __forceinline__ void cp16(uint32_t s, const void* g)
{
    asm volatile("cp.async.ca.shared.global [%0], [%1], 16;"
                 :: "r"(s), "l"(g));
}

__device__ __forceinline__ void ldsm4(uint32_t a, uint32_t* r)
{
    asm volatile("ldmatrix.sync.aligned.m8n8.x4.shared.b16 {%0,%1,%2,%3}, [%4];"
                 : "=r"(r[0]), "=r"(r[1]), "=r"(r[2]), "=r"(r[3]) : "r"(a));
}

__device__ __forceinline__ void mma16816(float* d, const uint32_t* a,
                                         const uint32_t* b)
{
    asm volatile(
        "mma.sync.aligned.m16n8k16.row.col.f32.f16.f16.f32 "
        "{%0,%1,%2,%3}, {%4,%5,%6,%7}, {%8,%9}, {%0,%1,%2,%3};"
        : "+f"(d[0]), "+f"(d[1]), "+f"(d[2]), "+f"(d[3])
        : "r"(a[0]), "r"(a[1]), "r"(a[2]), "r"(a[3]), "r"(b[0]), "r"(b[1]));
}

__global__ __launch_bounds__(512, 1)
void gemm_kernel(const float* __restrict__ bias, float* __restrict__ out)
{
    extern __shared__ char smem[];
    const uint32_t sbase = cvta_s(smem);

    const int tid  = threadIdx.x;
    const int lane = tid & 31;
    const int wid  = tid >> 5;
    const int m0   = blockIdx.x * 128;

    // loader: per stage A=1024 chunks (2/thr), B=2048 chunks (4/thr)
    const int rowA = tid >> 2;                 // 0..127
    const int cA0  = (tid & 3) * 2;            // 2 chunks
    const int rowB = tid >> 1;                 // 0..255
    const int cB0  = (tid & 1) * 4;            // 4 chunks
    const char* gA = (const char*)g_pa + ((size_t)(m0 + rowA) * K_) * 2;
    const char* gB = (const char*)g_wb + ((size_t)rowB * K_) * 2;

#define LOAD_STAGE(stage, buf)                                                 \
    {                                                                          \
        const uint32_t sbA = sbase + (buf) * STAGE_BYTES;                      \
        const uint32_t sbB = sbA + MATA_BYTES;                                 \
        const size_t gk = (size_t)(stage) * 128;                               \
        _Pragma("unroll")                                                      \
        for (int ci = 0; ci < 2; ci++)                                         \
            cp16(sbA + SWO(rowA, cA0 + ci), gA + gk + (cA0 + ci) * 16);        \
        _Pragma("unroll")                                                      \
        for (int ci = 0; ci < 4; ci++)                                         \
            cp16(sbB + SWO(rowB, cB0 + ci), gB + gk + (cB0 + ci) * 16);        \
    }

    // warp grid: 2 (m) x 8 (n); warp tile 64m x 32n
    const int wm = (wid & 1) * 64;
    const int wn = (wid >> 1) * 32;

    const int a_row  = lane & 15;
    const int a_col8 = (lane >> 4);
    const int b_row  = (lane & 7) + ((lane >> 4) << 3);
    const int b_col8 = (lane >> 3) & 1;

    float acc[4][4][4];
#pragma unroll
    for (int i = 0; i < 4; i++)
#pragma unroll
        for (int j = 0; j < 4; j++)
#pragma unroll
            for (int r = 0; r < 4; r++) acc[i][j][r] = 0.0f;

    LOAD_STAGE(0, 0);
    asm volatile("cp.async.commit_group;");
    LOAD_STAGE(1, 1);
    asm volatile("cp.async.commit_group;");

    for (int it = 0; it < NK; it++) {
        asm volatile("cp.async.wait_group 1;");
        __syncthreads();

        if (it + 2 < NK) LOAD_STAGE(it + 2, (it + 2) % 3);
        asm volatile("cp.async.commit_group;");   // exactly one commit per iter

        const uint32_t stg = sbase + (it % 3) * STAGE_BYTES;
        const uint32_t sA = stg;
        const uint32_t sB = stg + MATA_BYTES;

#pragma unroll
        for (int ks = 0; ks < 4; ks++) {
            const int ca = ks * 2 + a_col8;
            const int cb = ks * 2 + b_col8;
            uint32_t a[4][4], bfr[2][4];
#pragma unroll
            for (int i = 0; i < 4; i++)
                ldsm4(sA + SWO(wm + i * 16 + a_row, ca), a[i]);
#pragma unroll
            for (int j2 = 0; j2 < 2; j2++)
                ldsm4(sB + SWO(wn + j2 * 16 + b_row, cb), bfr[j2]);
#pragma unroll
            for (int i = 0; i < 4; i++)
#pragma unroll
                for (int j = 0; j < 4; j++)
                    mma16816(acc[i][j], a[i], &bfr[j >> 1][(j & 1) * 2]);
        }
    }

    asm volatile("cp.async.wait_group 0;");
    __syncthreads();

    // ---- epilogue: four 64-o quarters staged through smem ----
    float* eb = (float*)smem;            // [64 o][132 m] floats = 33.8 KB
    const int bidx = m0 >> 10;
    const int pq0  = m0 & 1023;

#pragma unroll
    for (int h = 0; h < 4; h++) {
        const int oh0 = h * 64;
        if (wn >= oh0 && wn < oh0 + 64) {
#pragma unroll
            for (int i = 0; i < 4; i++) {
                int ml = wm + i * 16 + (lane >> 2);
#pragma unroll
                for (int j = 0; j < 4; j++) {
                    int ol = wn - oh0 + j * 8 + (lane & 3) * 2;
                    eb[(size_t)ol * 132 + ml]           = acc[i][j][0];
                    eb[(size_t)(ol + 1) * 132 + ml]     = acc[i][j][1];
                    eb[(size_t)ol * 132 + ml + 8]       = acc[i][j][2];
                    eb[(size_t)(ol + 1) * 132 + ml + 8] = acc[i][j][3];
                }
            }
        }
        __syncthreads();

        // 512 threads store 64 o x 128 m: 16 m-floats per thread
        const int oo  = tid >> 3;            // 0..63
        const int oct = tid & 7;             // 16 m each
        const int og  = oh0 + oo;
        const float bv = __ldg(bias + og);
        float* op = out + (size_t)bidx * (O_ * 1024)
                  + (size_t)og * 1024 + pq0 + oct * 16;
        const float* sp = eb + (size_t)oo * 132 + oct * 16;
#pragma unroll
        for (int i = 0; i < 4; i++) {
            float4 vv = *(const float4*)(sp + i * 4);
            vv.x += bv; vv.y += bv; vv.z += bv; vv.w += bv;
            *(float4*)(op + i * 4) = vv;
        }
        __syncthreads();
    }
#undef LOAD_STAGE
}

// ---------------------------------------------------------------------------
extern "C" void kernel_launch(void* const* d_in, const int* in_sizes, int n_in,
                              void* d_out, int out_size)
{
    const float* x    = (const float*)d_in[0];
    const float* w    = (const float*)d_in[1];
    const float* bias = (const float*)d_in[2];
    const float* sh   = (const float*)d_in[3];
    const float* sw   = (const float*)d_in[4];
    float* out = (float*)d_out;

    cudaFuncSetAttribute(im2col_kernel,
                         cudaFuncAttributeMaxDynamicSharedMemorySize, IM2COL_SMEM);
    cudaFuncSetAttribute(gemm_kernel,
                         cudaFuncAttributeMaxDynamicSharedMemorySize, SMEM_BYTES);

    im2col_kernel<<<1024, 256, IM2COL_SMEM>>>(x, sh, sw);
    wconv_kernel<<<(O_ * K_) / 256, 256>>>(w);
    gemm_kernel<<<256, 512, SMEM_BYTES>>>(bias, out);
}